// round 2
// baseline (speedup 1.0000x reference)
#include <cuda_runtime.h>
#include <mma.h>
#include <math.h>
#include <stdint.h>

using namespace nvcuda;

// Problem constants
#define NB   16
#define NH   128
#define NW   128
#define NC   64
#define NC2  128
#define NK   7
#define NT   16

// ---------------------------------------------------------------------------
// Device scratch (no allocations allowed)
// ---------------------------------------------------------------------------
__device__ float2 d_tw[128];                  // twiddle table e^{-2pi i k/128}
__device__ float  d_tr[2][NK][NW][NC];        // stage-1 partial DFT, real
__device__ float  d_ti[2][NK][NW][NC];        // stage-1 partial DFT, imag
__device__ float  d_Ar[NH * NW * NC];
__device__ float  d_Ai[NH * NW * NC];
__device__ float  d_Br[NH * NW * NC];
__device__ float  d_Bi[NH * NW * NC];

// ---------------------------------------------------------------------------
// S0: twiddle table (accurate sincos, 128 threads, once per replay)
// ---------------------------------------------------------------------------
__global__ void k_twiddle() {
    int i = threadIdx.x;
    float ang = -2.0f * 3.14159265358979323846f * (float)i / 128.0f;
    float s, c;
    sincosf(ang, &s, &c);
    d_tw[i] = make_float2(c, s);
}

// ---------------------------------------------------------------------------
// S1: t[tensor][p][v][c] = sum_q kern[c,p,q] * w^{v(60+q)}
// ---------------------------------------------------------------------------
__global__ void k_stage1(const float* __restrict__ Are, const float* __restrict__ Aim,
                         const float* __restrict__ Bre, const float* __restrict__ Bim) {
    int id = blockIdx.x * blockDim.x + threadIdx.x;   // 7*128*64 = 57344
    if (id >= NK * NW * NC) return;
    int c = id & 63;
    int v = (id >> 6) & 127;
    int p = id >> 13;

    const float* Rr[2] = {Are, Bre};
    const float* Ri[2] = {Aim, Bim};
#pragma unroll
    for (int t = 0; t < 2; t++) {
        float accr = 0.0f, acci = 0.0f;
#pragma unroll
        for (int q = 0; q < NK; q++) {
            int k = (v * (60 + q)) & 127;
            float2 w = d_tw[k];
            float kr = Rr[t][c * 49 + p * 7 + q];
            float ki = Ri[t][c * 49 + p * 7 + q];
            accr += kr * w.x - ki * w.y;
            acci += kr * w.y + ki * w.x;
        }
        d_tr[t][p][v][c] = accr;
        d_ti[t][p][v][c] = acci;
    }
}

// ---------------------------------------------------------------------------
// S2: F[c,u,v] = sum_p t[p][v][c] * w^{u(60+p)}; stabilize A; store [h][w][c]
// ---------------------------------------------------------------------------
__global__ void k_stage2() {
    int id = blockIdx.x * blockDim.x + threadIdx.x;   // 128*128*64 = 1048576
    int c = id & 63;
    int v = (id >> 6) & 127;
    int u = id >> 13;

    float ar = 0.0f, ai = 0.0f, br = 0.0f, bi = 0.0f;
#pragma unroll
    for (int p = 0; p < NK; p++) {
        int k = (u * (60 + p)) & 127;
        float2 w = d_tw[k];
        float tr = d_tr[0][p][v][c];
        float ti = d_ti[0][p][v][c];
        ar += tr * w.x - ti * w.y;
        ai += tr * w.y + ti * w.x;
        tr = d_tr[1][p][v][c];
        ti = d_ti[1][p][v][c];
        br += tr * w.x - ti * w.y;
        bi += tr * w.y + ti * w.x;
    }
    // stabilization of A (accurate exp; runs once over 1M elems, cheap)
    float mag = sqrtf(ar * ar + ai * ai + 1e-8f);
    float sig = 1.0f / (1.0f + expf(-mag));
    float scale = 0.95f * sig / (mag + 1e-8f);
    int o = (u * NW + v) * NC + c;
    d_Ar[o] = ar * scale;
    d_Ai[o] = ai * scale;
    d_Br[o] = br;
    d_Bi[o] = bi;
}

// ---------------------------------------------------------------------------
// Main fused kernel: one CTA per (b,h) row of 128 pixels.
//   Phase 1: tf32 WMMA GEMM  G = X @ [Wi|Wd|Wf] + bias (bias via acc-init tile)
//   Phase 2: activations on fragments, products staged in smem
//   Phase 3: per-element 16-step recurrence, write output
// ---------------------------------------------------------------------------
#define LDX 132
#define SM_XS 0
#define SM_WS 16896
#define SM_PG 33792
#define SM_BB 50688
#define SM_FLOATS 52800           // 211200 bytes

extern __shared__ float sm[];

__device__ __forceinline__ float fast_sigmoid(float z) {
    return 1.0f / (1.0f + __expf(-z));
}

__global__ void __launch_bounds__(256, 1)
k_main(const float* __restrict__ x,
       const float* __restrict__ Wf, const float* __restrict__ bf,
       const float* __restrict__ Wi, const float* __restrict__ bi,
       const float* __restrict__ Wd, const float* __restrict__ bd,
       float* __restrict__ out) {
    float* xs = sm + SM_XS;   // [128][132] x tile (tf32-rounded)
    float* ws = sm + SM_WS;   // [128][132] W chunk; later fg storage
    float* pg = sm + SM_PG;   // [128][132] ig, then p = 0.1*softplus*ig
    float* bb = sm + SM_BB;   // [16][132]  bias broadcast tile

    const int tid = threadIdx.x;
    const int bh = blockIdx.x;          // b*128 + h
    const int h = bh & 127;
    const float* xbase = x + (size_t)bh * (NW * NC2);

    // load + tf32-round x tile
    for (int i = tid; i < NW * NC2; i += 256) {
        int w = i >> 7, k = i & 127;
        xs[w * LDX + k] = wmma::__float_to_tf32(xbase[i]);
    }

    const int warp = tid >> 5;
    const int wm = (warp & 3) * 32;     // M offset of warp tile (32 rows)
    const int wn = (warp >> 2) * 64;    // N offset of warp tile (64 cols)

    wmma::fragment<wmma::accumulator, 16, 16, 8, float> acc[2][4];
    wmma::fragment<wmma::matrix_a, 16, 16, 8, wmma::precision::tf32, wmma::row_major> af[2];
    wmma::fragment<wmma::matrix_b, 16, 16, 8, wmma::precision::tf32, wmma::row_major> bfr[4];

    const float* Wp[3] = {Wi, Wd, Wf};
    const float* bp[3] = {bi, bd, bf};

    for (int ch = 0; ch < 3; ch++) {
        __syncthreads();   // previous users of ws (and xs on first iter) done
        const float* W = Wp[ch];
        for (int i = tid; i < NC2 * NC2; i += 256) {
            int k = i >> 7, n = i & 127;
            ws[k * LDX + n] = wmma::__float_to_tf32(W[i]);
        }
        float badd = (ch == 2) ? 2.0f : 0.0f;   // forget gate: sigmoid(.. + 2)
        for (int i = tid; i < 16 * NC2; i += 256) {
            int r = i >> 7, n = i & 127;
            bb[r * LDX + n] = bp[ch][n] + badd;
        }
        __syncthreads();

        // init accumulators from bias tile
#pragma unroll
        for (int i = 0; i < 2; i++)
#pragma unroll
            for (int j = 0; j < 4; j++)
                wmma::load_matrix_sync(acc[i][j], bb + (wn + j * 16), LDX,
                                       wmma::mem_row_major);

        // K loop
#pragma unroll 4
        for (int k0 = 0; k0 < NC2; k0 += 8) {
#pragma unroll
            for (int i = 0; i < 2; i++)
                wmma::load_matrix_sync(af[i], xs + (wm + i * 16) * LDX + k0, LDX);
#pragma unroll
            for (int j = 0; j < 4; j++)
                wmma::load_matrix_sync(bfr[j], ws + k0 * LDX + wn + j * 16, LDX);
#pragma unroll
            for (int i = 0; i < 2; i++)
#pragma unroll
                for (int j = 0; j < 4; j++)
                    wmma::mma_sync(acc[i][j], af[i], bfr[j], acc[i][j]);
        }

        if (ch == 0) {
            // input gate: sigmoid, stash in pg
#pragma unroll
            for (int i = 0; i < 2; i++)
#pragma unroll
                for (int j = 0; j < 4; j++) {
                    for (int e = 0; e < acc[i][j].num_elements; e++)
                        acc[i][j].x[e] = fast_sigmoid(acc[i][j].x[e]);
                    wmma::store_matrix_sync(pg + (wm + i * 16) * LDX + wn + j * 16,
                                            acc[i][j], LDX, wmma::mem_row_major);
                }
            __syncwarp();   // cross-lane smem visibility before ch==1 reads
        } else if (ch == 1) {
            // p = 0.1 * softplus(pre) * ig  (same warp-tile addrs as ch==0)
            wmma::fragment<wmma::accumulator, 16, 16, 8, float> igf;
#pragma unroll
            for (int i = 0; i < 2; i++)
#pragma unroll
                for (int j = 0; j < 4; j++) {
                    wmma::load_matrix_sync(igf, pg + (wm + i * 16) * LDX + wn + j * 16,
                                           LDX, wmma::mem_row_major);
                    for (int e = 0; e < acc[i][j].num_elements; e++) {
                        float z = acc[i][j].x[e];
                        float sp = (z > 20.0f) ? z : log1pf(__expf(z));
                        acc[i][j].x[e] = 0.1f * sp * igf.x[e];
                    }
                    wmma::store_matrix_sync(pg + (wm + i * 16) * LDX + wn + j * 16,
                                            acc[i][j], LDX, wmma::mem_row_major);
                }
        } else {
            // forget gate: sigmoid; overwrite ws (all warps done reading it)
            __syncthreads();
#pragma unroll
            for (int i = 0; i < 2; i++)
#pragma unroll
                for (int j = 0; j < 4; j++) {
                    for (int e = 0; e < acc[i][j].num_elements; e++)
                        acc[i][j].x[e] = fast_sigmoid(acc[i][j].x[e]);
                    wmma::store_matrix_sync(ws + (wm + i * 16) * LDX + wn + j * 16,
                                            acc[i][j], LDX, wmma::mem_row_major);
                }
        }
    }
    __syncthreads();

    // ---------------- recurrence epilogue ----------------
    const int c = tid & 63;
    const int w0 = tid >> 6;
    const size_t outbase = (size_t)bh * (NW * NC2);
    const int hw_base = h * NW;

    for (int w = w0; w < NW; w += 4) {
        float x_r = xs[w * LDX + c];
        float x_i = xs[w * LDX + c + 64];
        float p_r = pg[w * LDX + c];
        float p_i = pg[w * LDX + c + 64];
        float fg_r = ws[w * LDX + c];
        float fg_i = ws[w * LDX + c + 64];

        int o = (hw_base + w) * NC + c;
        float Ar = d_Ar[o], Ai = d_Ai[o];
        float Br = d_Br[o], Bi = d_Bi[o];

        float Bx_r = Br * x_r - Bi * x_i;
        float Bx_i = Br * x_i + Bi * x_r;
        float inp_r = p_r * Bx_r;
        float inp_i = p_i * Bx_i;

        float Mrr = fg_r * Ar;
        float Mri = -fg_r * Ai;
        float Mir = fg_i * Ai;
        float Mii = fg_i * Ar;

        // h1 = inp (h0 = 0), then 15 more steps -> h16
        float hr = inp_r, hi = inp_i;
#pragma unroll
        for (int t = 1; t < NT; t++) {
            float nr = fmaf(Mrr, hr, fmaf(Mri, hi, inp_r));
            float ni = fmaf(Mir, hr, fmaf(Mii, hi, inp_i));
            hr = nr;
            hi = ni;
        }
        out[outbase + w * NC2 + c] = hr;
        out[outbase + w * NC2 + c + 64] = hi;
    }
}

// ---------------------------------------------------------------------------
// Launch
// ---------------------------------------------------------------------------
extern "C" void kernel_launch(void* const* d_in, const int* in_sizes, int n_in,
                              void* d_out, int out_size) {
    (void)in_sizes; (void)n_in; (void)out_size;
    const float* x      = (const float*)d_in[0];
    const float* Wf     = (const float*)d_in[1];
    const float* bf     = (const float*)d_in[2];
    const float* Wi     = (const float*)d_in[3];
    const float* bi     = (const float*)d_in[4];
    const float* Wd     = (const float*)d_in[5];
    const float* bd     = (const float*)d_in[6];
    const float* A_real = (const float*)d_in[7];
    const float* A_imag = (const float*)d_in[8];
    const float* B_real = (const float*)d_in[9];
    const float* B_imag = (const float*)d_in[10];
    float* out = (float*)d_out;

    cudaFuncSetAttribute(k_main, cudaFuncAttributeMaxDynamicSharedMemorySize,
                         SM_FLOATS * (int)sizeof(float));

    k_twiddle<<<1, 128>>>();
    k_stage1<<<(NK * NW * NC + 255) / 256, 256>>>(A_real, A_imag, B_real, B_imag);
    k_stage2<<<(NH * NW * NC) / 256, 256>>>();
    k_main<<<NB * NH, 256, SM_FLOATS * (int)sizeof(float)>>>(
        x, Wf, bf, Wi, bi, Wd, bd, out);
}

// round 3
// speedup vs baseline: 1.7947x; 1.7947x over previous
#include <cuda_runtime.h>
#include <mma.h>
#include <math.h>
#include <stdint.h>

using namespace nvcuda;

// Problem constants
#define NB   16
#define NH   128
#define NW   128
#define NC   64
#define NC2  128
#define NK   7
#define NT   16

// ---------------------------------------------------------------------------
// Device scratch (no allocations allowed)
// ---------------------------------------------------------------------------
__device__ float2 d_tw[128];                  // twiddle table e^{-2pi i k/128}
__device__ float  d_tr[2][NK][NW][NC];        // stage-1 partial DFT, real
__device__ float  d_ti[2][NK][NW][NC];        // stage-1 partial DFT, imag
__device__ float  d_Ar[NH * NW * NC];
__device__ float  d_Ai[NH * NW * NC];
__device__ float  d_Br[NH * NW * NC];
__device__ float  d_Bi[NH * NW * NC];

// ---------------------------------------------------------------------------
// S0: twiddle table
// ---------------------------------------------------------------------------
__global__ void k_twiddle() {
    int i = threadIdx.x;
    float ang = -2.0f * 3.14159265358979323846f * (float)i / 128.0f;
    float s, c;
    sincosf(ang, &s, &c);
    d_tw[i] = make_float2(c, s);
}

// ---------------------------------------------------------------------------
// S1: t[tensor][p][v][c] = sum_q kern[c,p,q] * w^{v(60+q)}
// ---------------------------------------------------------------------------
__global__ void k_stage1(const float* __restrict__ Are, const float* __restrict__ Aim,
                         const float* __restrict__ Bre, const float* __restrict__ Bim) {
    int id = blockIdx.x * blockDim.x + threadIdx.x;   // 7*128*64 = 57344
    if (id >= NK * NW * NC) return;
    int c = id & 63;
    int v = (id >> 6) & 127;
    int p = id >> 13;

    const float* Rr[2] = {Are, Bre};
    const float* Ri[2] = {Aim, Bim};
#pragma unroll
    for (int t = 0; t < 2; t++) {
        float accr = 0.0f, acci = 0.0f;
#pragma unroll
        for (int q = 0; q < NK; q++) {
            int k = (v * (60 + q)) & 127;
            float2 w = d_tw[k];
            float kr = Rr[t][c * 49 + p * 7 + q];
            float ki = Ri[t][c * 49 + p * 7 + q];
            accr += kr * w.x - ki * w.y;
            acci += kr * w.y + ki * w.x;
        }
        d_tr[t][p][v][c] = accr;
        d_ti[t][p][v][c] = acci;
    }
}

// ---------------------------------------------------------------------------
// S2: F[c,u,v] = sum_p t[p][v][c] * w^{u(60+p)}; stabilize A; store [h][w][c]
// ---------------------------------------------------------------------------
__global__ void k_stage2() {
    int id = blockIdx.x * blockDim.x + threadIdx.x;   // 1048576
    int c = id & 63;
    int v = (id >> 6) & 127;
    int u = id >> 13;

    float ar = 0.0f, ai = 0.0f, br = 0.0f, bi = 0.0f;
#pragma unroll
    for (int p = 0; p < NK; p++) {
        int k = (u * (60 + p)) & 127;
        float2 w = d_tw[k];
        float tr = d_tr[0][p][v][c];
        float ti = d_ti[0][p][v][c];
        ar += tr * w.x - ti * w.y;
        ai += tr * w.y + ti * w.x;
        tr = d_tr[1][p][v][c];
        ti = d_ti[1][p][v][c];
        br += tr * w.x - ti * w.y;
        bi += tr * w.y + ti * w.x;
    }
    float mag = sqrtf(ar * ar + ai * ai + 1e-8f);
    float sig = 1.0f / (1.0f + expf(-mag));
    float scale = 0.95f * sig / (mag + 1e-8f);
    int o = (u * NW + v) * NC + c;
    d_Ar[o] = ar * scale;
    d_Ai[o] = ai * scale;
    d_Br[o] = br;
    d_Bi[o] = bi;
}

// ---------------------------------------------------------------------------
// Main fused kernel: one CTA (512 threads, 16 warps) per (b,h) row.
//   GEMM chunks Wi -> Wd -> Wf, B-fragments loaded straight from gmem (L1/L2
//   cached, shared by all CTAs), A-fragments from smem x tile.
//   Gates staged in smem; per-element 16-step recurrence epilogue.
// ---------------------------------------------------------------------------
#define LDX 132
#define SM_XS 0
#define SM_GS 16896
#define SM_FS 33792
#define SM_BB 50688
#define SM_FLOATS 52800           // 211200 bytes

extern __shared__ float sm[];

__device__ __forceinline__ float fast_sigmoid(float z) {
    return 1.0f / (1.0f + __expf(-z));
}

__global__ void __launch_bounds__(512, 1)
k_main(const float* __restrict__ x,
       const float* __restrict__ Wf, const float* __restrict__ bf,
       const float* __restrict__ Wi, const float* __restrict__ bi,
       const float* __restrict__ Wd, const float* __restrict__ bd,
       float* __restrict__ out) {
    float* xs = sm + SM_XS;   // [128][132] x tile (tf32-rounded)
    float* gs = sm + SM_GS;   // [128][132] ig, then p = 0.1*softplus*ig
    float* fs = sm + SM_FS;   // [128][132] fg
    float* bb = sm + SM_BB;   // [16][132]  bias broadcast tile (rebuilt per chunk)

    const int tid = threadIdx.x;
    const int bh = blockIdx.x;          // b*128 + h
    const int h = bh & 127;
    const float* xbase = x + (size_t)bh * (NW * NC2);

    // load + tf32-round x tile
    for (int i = tid; i < NW * NC2; i += 512) {
        int w = i >> 7, k = i & 127;
        xs[w * LDX + k] = wmma::__float_to_tf32(xbase[i]);
    }

    const int warp = tid >> 5;
    const int wm = (warp & 3) * 32;     // M offset (4 tiles of 32 rows)
    const int wn = (warp >> 2) * 32;    // N offset (4 tiles of 32 cols)

    wmma::fragment<wmma::accumulator, 16, 16, 8, float> acc[2][2];
    wmma::fragment<wmma::matrix_a, 16, 16, 8, wmma::precision::tf32, wmma::row_major> af[2];
    wmma::fragment<wmma::matrix_b, 16, 16, 8, wmma::precision::tf32, wmma::row_major> bfr[2];

    const float* Wp[3] = {Wi, Wd, Wf};
    const float* bp[3] = {bi, bd, bf};

    for (int ch = 0; ch < 3; ch++) {
        __syncthreads();   // xs ready (ch0) / previous bb readers done (ch>0)
        const float badd = (ch == 2) ? 2.0f : 0.0f;
        {
            const float* b = bp[ch];
            for (int i = tid; i < 16 * NC2; i += 512) {
                int r = i >> 7, n = i & 127;
                bb[r * LDX + n] = b[n] + badd;
            }
        }
        __syncthreads();

        // init accumulators from bias tile
#pragma unroll
        for (int i = 0; i < 2; i++)
#pragma unroll
            for (int j = 0; j < 2; j++)
                wmma::load_matrix_sync(acc[i][j], bb + (wn + j * 16), LDX,
                                       wmma::mem_row_major);

        const float* W = Wp[ch];

        // K loop: A from smem (pre-rounded), B from gmem (round in regs)
#pragma unroll
        for (int k0 = 0; k0 < NC2; k0 += 8) {
#pragma unroll
            for (int j = 0; j < 2; j++) {
                wmma::load_matrix_sync(bfr[j], W + k0 * NC2 + wn + j * 16, NC2);
                for (int e = 0; e < bfr[j].num_elements; e++)
                    bfr[j].x[e] = wmma::__float_to_tf32(bfr[j].x[e]);
            }
#pragma unroll
            for (int i = 0; i < 2; i++)
                wmma::load_matrix_sync(af[i], xs + (wm + i * 16) * LDX + k0, LDX);
#pragma unroll
            for (int i = 0; i < 2; i++)
#pragma unroll
                for (int j = 0; j < 2; j++)
                    wmma::mma_sync(acc[i][j], af[i], bfr[j], acc[i][j]);
        }

        if (ch == 0) {
            // input gate: sigmoid -> gs
#pragma unroll
            for (int i = 0; i < 2; i++)
#pragma unroll
                for (int j = 0; j < 2; j++) {
                    for (int e = 0; e < acc[i][j].num_elements; e++)
                        acc[i][j].x[e] = fast_sigmoid(acc[i][j].x[e]);
                    wmma::store_matrix_sync(gs + (wm + i * 16) * LDX + wn + j * 16,
                                            acc[i][j], LDX, wmma::mem_row_major);
                }
            __syncwarp();   // warp re-reads its own tile in ch==1
        } else if (ch == 1) {
            // p = 0.1 * softplus(zd) * ig  (same warp-tile addrs as ch==0)
            wmma::fragment<wmma::accumulator, 16, 16, 8, float> igf;
#pragma unroll
            for (int i = 0; i < 2; i++)
#pragma unroll
                for (int j = 0; j < 2; j++) {
                    wmma::load_matrix_sync(igf, gs + (wm + i * 16) * LDX + wn + j * 16,
                                           LDX, wmma::mem_row_major);
                    for (int e = 0; e < acc[i][j].num_elements; e++) {
                        float z = acc[i][j].x[e];
                        float sp = (z > 20.0f) ? z : log1pf(__expf(z));
                        acc[i][j].x[e] = 0.1f * sp * igf.x[e];
                    }
                    wmma::store_matrix_sync(gs + (wm + i * 16) * LDX + wn + j * 16,
                                            acc[i][j], LDX, wmma::mem_row_major);
                }
        } else {
            // forget gate: sigmoid -> fs
#pragma unroll
            for (int i = 0; i < 2; i++)
#pragma unroll
                for (int j = 0; j < 2; j++) {
                    for (int e = 0; e < acc[i][j].num_elements; e++)
                        acc[i][j].x[e] = fast_sigmoid(acc[i][j].x[e]);
                    wmma::store_matrix_sync(fs + (wm + i * 16) * LDX + wn + j * 16,
                                            acc[i][j], LDX, wmma::mem_row_major);
                }
        }
    }
    __syncthreads();

    // ---------------- recurrence epilogue ----------------
    const int c = tid & 63;
    const int w0 = tid >> 6;            // 0..7
    const size_t outbase = (size_t)bh * (NW * NC2);
    const int hw_base = h * NW;

    for (int w = w0; w < NW; w += 8) {
        float x_r = xs[w * LDX + c];
        float x_i = xs[w * LDX + c + 64];
        float p_r = gs[w * LDX + c];
        float p_i = gs[w * LDX + c + 64];
        float fg_r = fs[w * LDX + c];
        float fg_i = fs[w * LDX + c + 64];

        int o = (hw_base + w) * NC + c;
        float Ar = d_Ar[o], Ai = d_Ai[o];
        float Br = d_Br[o], Bi = d_Bi[o];

        float Bx_r = Br * x_r - Bi * x_i;
        float Bx_i = Br * x_i + Bi * x_r;
        float inp_r = p_r * Bx_r;
        float inp_i = p_i * Bx_i;

        float Mrr = fg_r * Ar;
        float Mri = -fg_r * Ai;
        float Mir = fg_i * Ai;
        float Mii = fg_i * Ar;

        // h1 = inp (h0 = 0), then 15 more steps -> h16
        float hr = inp_r, hi = inp_i;
#pragma unroll
        for (int t = 1; t < NT; t++) {
            float nr = fmaf(Mrr, hr, fmaf(Mri, hi, inp_r));
            float ni = fmaf(Mir, hr, fmaf(Mii, hi, inp_i));
            hr = nr;
            hi = ni;
        }
        out[outbase + w * NC2 + c] = hr;
        out[outbase + w * NC2 + c + 64] = hi;
    }
}

// ---------------------------------------------------------------------------
// Launch
// ---------------------------------------------------------------------------
extern "C" void kernel_launch(void* const* d_in, const int* in_sizes, int n_in,
                              void* d_out, int out_size) {
    (void)in_sizes; (void)n_in; (void)out_size;
    const float* x      = (const float*)d_in[0];
    const float* Wf     = (const float*)d_in[1];
    const float* bf     = (const float*)d_in[2];
    const float* Wi     = (const float*)d_in[3];
    const float* bi     = (const float*)d_in[4];
    const float* Wd     = (const float*)d_in[5];
    const float* bd     = (const float*)d_in[6];
    const float* A_real = (const float*)d_in[7];
    const float* A_imag = (const float*)d_in[8];
    const float* B_real = (const float*)d_in[9];
    const float* B_imag = (const float*)d_in[10];
    float* out = (float*)d_out;

    cudaFuncSetAttribute(k_main, cudaFuncAttributeMaxDynamicSharedMemorySize,
                         SM_FLOATS * (int)sizeof(float));

    k_twiddle<<<1, 128>>>();
    k_stage1<<<(NK * NW * NC + 255) / 256, 256>>>(A_real, A_imag, B_real, B_imag);
    k_stage2<<<(NH * NW * NC) / 256, 256>>>();
    k_main<<<NB * NH, 512, SM_FLOATS * (int)sizeof(float)>>>(
        x, Wf, bf, Wi, bi, Wd, bd, out);
}